// round 5
// baseline (speedup 1.0000x reference)
#include <cuda_runtime.h>
#include <cuda_bf16.h>

#define NN 100000
#define EE 3200000

// ------------------------- scratch (static device memory) -------------------
__device__ float g_deg[NN];
__device__ float g_dinv[NN];
__device__ int   g_cnt[NN];
__device__ int   g_rowptr[NN + 1];
__device__ int   g_cursor[NN];
__device__ int2  g_csr[EE];            // (src, norm bits), grouped by dst
__device__ float g_x16[4][NN * 16];    // layer-1 hops h1..h4 (F=16)
__device__ float g_h[4][NN * 64];      // hidden hops h1..h4 (F=64)
__device__ float g_outA[NN * 64];      // layer outputs ping
__device__ float g_outB[NN * 64];      // layer outputs pong
__device__ int   g_is64;               // edge_index dtype flag (1 = int64)

// selector: 0..3 -> g_h[k], 4 -> g_outA, 5 -> g_outB
__device__ __forceinline__ float* buf64(int s) {
    switch (s) {
        case 0: return g_h[0];
        case 1: return g_h[1];
        case 2: return g_h[2];
        case 3: return g_h[3];
        case 4: return g_outA;
        default: return g_outB;
    }
}

// read edge endpoint robustly under either dtype
__device__ __forceinline__ int edge_at(const int* ei, int is64, long long pos) {
    if (is64) {
        long long v = ((const long long*)ei)[pos];
        return (int)v;
    }
    return ei[pos];
}

// ------------------------- dtype detect -------------------------------------
// int64 node ids < 2^17 => every odd 32-bit word is 0 (little-endian).
// For int32 data, 16 consecutive odd words all zero is ~impossible.
__global__ void k_detect(const int* __restrict__ ei) {
    int odd_nonzero = 0;
    #pragma unroll
    for (int i = 0; i < 16; i++)
        if (ei[2 * i + 1] != 0) odd_nonzero = 1;
    g_is64 = odd_nonzero ? 0 : 1;
}

// ------------------------- CSR build ----------------------------------------
__global__ void k_init() {
    int i = blockIdx.x * blockDim.x + threadIdx.x;
    if (i < NN) { g_deg[i] = 0.f; g_cnt[i] = 0; }
}

__global__ void k_degcnt(const int* __restrict__ ei,
                         const float* __restrict__ ew) {
    int e = blockIdx.x * blockDim.x + threadIdx.x;
    if (e < EE) {
        int is64 = g_is64;
        int d = edge_at(ei, is64, (long long)EE + e);
        if ((unsigned)d < (unsigned)NN) {       // never trap on bad data
            atomicAdd(&g_deg[d], ew[e]);
            atomicAdd(&g_cnt[d], 1);
        }
    }
}

__global__ void k_dinv() {
    int i = blockIdx.x * blockDim.x + threadIdx.x;
    if (i < NN) {
        float d = g_deg[i];
        g_dinv[i] = (d > 0.f) ? rsqrtf(d) : 0.f;
    }
}

// single-block exclusive scan of g_cnt -> g_rowptr (+ copy to g_cursor)
__global__ void k_scan() {
    __shared__ int ssum[1024];
    const int C = 98;                       // 1024*98 = 100352 >= NN
    int t = threadIdx.x;
    int lo = t * C;
    int hi = lo + C; if (hi > NN) hi = NN;
    int s = 0;
    for (int i = lo; i < hi; i++) s += g_cnt[i];
    ssum[t] = s;
    __syncthreads();
    for (int off = 1; off < 1024; off <<= 1) {
        int add = (t >= off) ? ssum[t - off] : 0;
        __syncthreads();
        ssum[t] += add;
        __syncthreads();
    }
    int run = (t > 0) ? ssum[t - 1] : 0;    // exclusive prefix
    for (int i = lo; i < hi; i++) {
        g_rowptr[i] = run;
        g_cursor[i] = run;
        run += g_cnt[i];
    }
    if (t == 1023) g_rowptr[NN] = ssum[1023];
}

__global__ void k_scatter(const int* __restrict__ ei,
                          const float* __restrict__ ew) {
    int e = blockIdx.x * blockDim.x + threadIdx.x;
    if (e < EE) {
        int is64 = g_is64;
        int s = edge_at(ei, is64, e);
        int d = edge_at(ei, is64, (long long)EE + e);
        if ((unsigned)s < (unsigned)NN && (unsigned)d < (unsigned)NN) {
            float nm = g_dinv[s] * ew[e] * g_dinv[d];
            int pos = atomicAdd(&g_cursor[d], 1);
            g_csr[pos] = make_int2(s, __float_as_int(nm));
        }
    }
}

// ------------------------- propagation (warp per node) ----------------------
// F=64: each lane owns a float2 of the feature row.
__global__ void k_prop64(int in_sel, int out_sel) {
    int gid = blockIdx.x * blockDim.x + threadIdx.x;
    int n = gid >> 5, lane = gid & 31;
    const float2* h2 = (const float2*)buf64(in_sel);
    float2* o2 = (float2*)g_h[out_sel];
    int s0 = g_rowptr[n], s1 = g_rowptr[n + 1];
    float ax = 0.f, ay = 0.f;
    for (int base = s0; base < s1; base += 32) {
        int idx = base + lane;
        int2 ent = make_int2(0, 0);
        if (idx < s1) ent = g_csr[idx];
        int m = s1 - base; if (m > 32) m = 32;
        #pragma unroll 4
        for (int j = 0; j < m; j++) {
            int   ss = __shfl_sync(0xffffffffu, ent.x, j);
            float ww = __int_as_float(__shfl_sync(0xffffffffu, ent.y, j));
            float2 v = h2[ss * 32 + lane];
            ax += ww * v.x;
            ay += ww * v.y;
        }
    }
    o2[n * 32 + lane] = make_float2(ax, ay);
}

// F=16: 16 lanes cover features, two edge slots per iteration.
// in_sel < 0 -> external input x; else g_x16[in_sel]. Output: g_x16[out_sel].
__global__ void k_prop16(const float* __restrict__ xext, int in_sel, int out_sel) {
    int gid = blockIdx.x * blockDim.x + threadIdx.x;
    int n = gid >> 5, lane = gid & 31;
    int feat = lane & 15, slot = lane >> 4;
    const float* hin = (in_sel < 0) ? xext : g_x16[in_sel];
    float* hout = g_x16[out_sel];
    int s0 = g_rowptr[n], s1 = g_rowptr[n + 1];
    float acc = 0.f;
    for (int base = s0; base < s1; base += 32) {
        int idx = base + lane;
        int2 ent = make_int2(0, 0);
        if (idx < s1) ent = g_csr[idx];
        int m = s1 - base; if (m > 32) m = 32;
        #pragma unroll 4
        for (int j = 0; j < m; j += 2) {
            int e = j + slot;          // invalid slots carry w = 0
            int   ss = __shfl_sync(0xffffffffu, ent.x, e);
            float ww = __int_as_float(__shfl_sync(0xffffffffu, ent.y, e));
            acc += ww * hin[ss * 16 + feat];
        }
    }
    acc += __shfl_xor_sync(0xffffffffu, acc, 16);
    if (lane < 16) hout[n * 16 + lane] = acc;
}

// ------------------------- fused hop-GEMM + bias + LeakyReLU ----------------
// out[n][j] = leaky( b[j] + sum_{k=0..4} sum_i h_k[n][i] * W[k][i][j] )
// tile: 128 nodes x 64 j per block (256 threads); thread: 8 nodes x 4 j.

__device__ __forceinline__ void mm_body(const float* const* hs, int F,
                                        const float* __restrict__ W,
                                        const float* __restrict__ b,
                                        float* __restrict__ out,
                                        float* shW) {
    int t  = threadIdx.x;
    int n0 = blockIdx.x * 128;
    int tn = (t & 15) * 8;
    int tj = (t >> 4) * 4;

    float acc[8][4];
    #pragma unroll
    for (int p = 0; p < 8; p++)
        #pragma unroll
        for (int jj = 0; jj < 4; jj++) acc[p][jj] = 0.f;

    #pragma unroll
    for (int k = 0; k < 5; k++) {
        __syncthreads();
        {
            const float4* Wk  = (const float4*)(W + k * F * 64);
            float4*       sh4 = (float4*)shW;
            for (int idx = t; idx < F * 16; idx += 256) sh4[idx] = Wk[idx];
        }
        __syncthreads();
        const float* hk = hs[k];
        for (int ic = 0; ic < F / 4; ic++) {
            float4 a[8];
            #pragma unroll
            for (int p = 0; p < 8; p++) {
                int n = n0 + tn + p;
                a[p] = (n < NN) ? *(const float4*)(hk + n * F + ic * 4)
                                : make_float4(0.f, 0.f, 0.f, 0.f);
            }
            #pragma unroll
            for (int q = 0; q < 4; q++) {
                int i = ic * 4 + q;
                float4 bv = *(const float4*)(shW + i * 64 + tj);
                #pragma unroll
                for (int p = 0; p < 8; p++) {
                    float av = (q == 0) ? a[p].x : (q == 1) ? a[p].y
                             : (q == 2) ? a[p].z : a[p].w;
                    acc[p][0] += av * bv.x;
                    acc[p][1] += av * bv.y;
                    acc[p][2] += av * bv.z;
                    acc[p][3] += av * bv.w;
                }
            }
        }
    }
    float4 bb = *(const float4*)(b + tj);
    #pragma unroll
    for (int p = 0; p < 8; p++) {
        int n = n0 + tn + p;
        if (n < NN) {
            float4 y;
            y.x = acc[p][0] + bb.x;  y.x = (y.x >= 0.f) ? y.x : 0.01f * y.x;
            y.y = acc[p][1] + bb.y;  y.y = (y.y >= 0.f) ? y.y : 0.01f * y.y;
            y.z = acc[p][2] + bb.z;  y.z = (y.z >= 0.f) ? y.z : 0.01f * y.z;
            y.w = acc[p][3] + bb.w;  y.w = (y.w >= 0.f) ? y.w : 0.01f * y.w;
            *(float4*)(out + n * 64 + tj) = y;
        }
    }
}

// layer 1: hops = {x, g_x16[0..3]}, F=16, writes g_outA
__global__ void k_mm16(const float* __restrict__ x,
                       const float* __restrict__ W,
                       const float* __restrict__ b) {
    __shared__ float shW[16 * 64];
    const float* hs[5] = {x, g_x16[0], g_x16[1], g_x16[2], g_x16[3]};
    mm_body(hs, 16, W, b, g_outA, shW);
}

// layers 2/3: hops = {in(A/B), g_h[0..3]}, F=64, writes out(A/B)
__global__ void k_mm64(int in_sel, const float* __restrict__ W,
                       const float* __restrict__ b, int out_sel) {
    __shared__ float shW[64 * 64];
    const float* hs[5] = {buf64(in_sel), g_h[0], g_h[1], g_h[2], g_h[3]};
    mm_body(hs, 64, W, b, buf64(out_sel), shW);
}

// ------------------------- final linear head (reads g_outA) -----------------
__global__ void k_final(const float* __restrict__ Wout,
                        const float* __restrict__ bout,
                        float* __restrict__ out) {
    int gid = blockIdx.x * blockDim.x + threadIdx.x;
    int n = gid >> 5, lane = gid & 31;
    float2 v = ((const float2*)g_outA)[n * 32 + lane];
    float2 w = ((const float2*)Wout)[lane];
    float a = v.x * w.x + v.y * w.y;
    #pragma unroll
    for (int off = 16; off > 0; off >>= 1)
        a += __shfl_xor_sync(0xffffffffu, a, off);
    if (lane == 0) out[n] = a + bout[0];
}

// ------------------------- launch -------------------------------------------
extern "C" void kernel_launch(void* const* d_in, const int* in_sizes, int n_in,
                              void* d_out, int out_size) {
    const float* x    = (const float*)d_in[0];
    const int*   ei   = (const int*)d_in[1];     // dtype auto-detected
    const float* ew   = (const float*)d_in[2];
    const float* W1   = (const float*)d_in[4];
    const float* b1   = (const float*)d_in[5];
    const float* W2   = (const float*)d_in[6];
    const float* b2   = (const float*)d_in[7];
    const float* Wout = (const float*)d_in[8];
    const float* bout = (const float*)d_in[9];
    float*       out  = (float*)d_out;

    const int NB_N = (NN + 255) / 256;
    const int NB_E = (EE + 255) / 256;
    const int NB_W = (NN * 32) / 256;       // warp-per-node: 12500 blocks
    const int NB_M = (NN + 127) / 128;      // mm kernels: 782 blocks

    // dtype detect + CSR + norm build
    k_detect <<<1, 1>>>(ei);
    k_init   <<<NB_N, 256>>>();
    k_degcnt <<<NB_E, 256>>>(ei, ew);
    k_dinv   <<<NB_N, 256>>>();
    k_scan   <<<1, 1024>>>();
    k_scatter<<<NB_E, 256>>>(ei, ew);

    // Layer 1 (F_IN=16 -> 64), hops in g_x16, out -> g_outA (sel 4)
    k_prop16<<<NB_W, 256>>>(x, -1, 0);
    k_prop16<<<NB_W, 256>>>(x,  0, 1);
    k_prop16<<<NB_W, 256>>>(x,  1, 2);
    k_prop16<<<NB_W, 256>>>(x,  2, 3);
    k_mm16  <<<NB_M, 256>>>(x, W1, b1);

    // Layer 2 (64 -> 64): in A(4) -> out B(5)
    k_prop64<<<NB_W, 256>>>(4, 0);
    k_prop64<<<NB_W, 256>>>(0, 1);
    k_prop64<<<NB_W, 256>>>(1, 2);
    k_prop64<<<NB_W, 256>>>(2, 3);
    k_mm64  <<<NB_M, 256>>>(4, W2, b2, 5);

    // Layer 3 (64 -> 64): in B(5) -> out A(4)
    k_prop64<<<NB_W, 256>>>(5, 0);
    k_prop64<<<NB_W, 256>>>(0, 1);
    k_prop64<<<NB_W, 256>>>(1, 2);
    k_prop64<<<NB_W, 256>>>(2, 3);
    k_mm64  <<<NB_M, 256>>>(5, W2 + 5 * 64 * 64, b2 + 64, 4);

    // Regression head (reads g_outA)
    k_final<<<NB_W, 256>>>(Wout, bout, out);
}

// round 7
// speedup vs baseline: 1.0231x; 1.0231x over previous
#include <cuda_runtime.h>
#include <cuda_fp16.h>

#define NN 100000
#define EE 3200000

// ------------------------- scratch (static device memory) -------------------
__device__ float  g_deg[NN];
__device__ float  g_dinv[NN];
__device__ int    g_cnt[NN];
__device__ int    g_rowptr[NN + 1];
__device__ int    g_cursor[NN];
__device__ int2   g_csr[EE];             // (src, norm bits), grouped by dst
__device__ __half g_x16h[4][NN * 16];    // layer-1 hops h1..h4 (F=16, fp16)
__device__ __half g_hh[4][NN * 64];      // hidden hops h1..h4 (F=64, fp16)
__device__ float  g_outA[NN * 64];       // layer outputs ping (fp32)
__device__ float  g_outB[NN * 64];       // layer outputs pong (fp32)
__device__ __half g_outAh[NN * 64];      // fp16 shadow of outA (prop input)
__device__ __half g_outBh[NN * 64];      // fp16 shadow of outB
__device__ int    g_is64;                // edge_index dtype flag (1 = int64)

// fp16 buffer selector: 0..3 -> g_hh[k], 4 -> g_outAh, 5 -> g_outBh
__device__ __forceinline__ const __half* hbuf64(int s) {
    switch (s) {
        case 0: return g_hh[0];
        case 1: return g_hh[1];
        case 2: return g_hh[2];
        case 3: return g_hh[3];
        case 4: return g_outAh;
        default: return g_outBh;
    }
}

__device__ __forceinline__ int edge_at(const int* ei, int is64, long long pos) {
    if (is64) return (int)((const long long*)ei)[pos];
    return ei[pos];
}

// ------------------------- dtype detect -------------------------------------
__global__ void k_detect(const int* __restrict__ ei) {
    int odd_nonzero = 0;
    #pragma unroll
    for (int i = 0; i < 16; i++)
        if (ei[2 * i + 1] != 0) odd_nonzero = 1;
    g_is64 = odd_nonzero ? 0 : 1;
}

// ------------------------- CSR build ----------------------------------------
__global__ void k_init() {
    int i = blockIdx.x * blockDim.x + threadIdx.x;
    if (i < NN) { g_deg[i] = 0.f; g_cnt[i] = 0; }
}

__global__ void k_degcnt(const int* __restrict__ ei,
                         const float* __restrict__ ew) {
    int e = blockIdx.x * blockDim.x + threadIdx.x;
    if (e < EE) {
        int is64 = g_is64;
        int d = edge_at(ei, is64, (long long)EE + e);
        if ((unsigned)d < (unsigned)NN) {
            atomicAdd(&g_deg[d], ew[e]);
            atomicAdd(&g_cnt[d], 1);
        }
    }
}

__global__ void k_dinv() {
    int i = blockIdx.x * blockDim.x + threadIdx.x;
    if (i < NN) {
        float d = g_deg[i];
        g_dinv[i] = (d > 0.f) ? rsqrtf(d) : 0.f;
    }
}

__global__ void k_scan() {
    __shared__ int ssum[1024];
    const int C = 98;                       // 1024*98 >= NN
    int t = threadIdx.x;
    int lo = t * C;
    int hi = lo + C; if (hi > NN) hi = NN;
    int s = 0;
    for (int i = lo; i < hi; i++) s += g_cnt[i];
    ssum[t] = s;
    __syncthreads();
    for (int off = 1; off < 1024; off <<= 1) {
        int add = (t >= off) ? ssum[t - off] : 0;
        __syncthreads();
        ssum[t] += add;
        __syncthreads();
    }
    int run = (t > 0) ? ssum[t - 1] : 0;
    for (int i = lo; i < hi; i++) {
        g_rowptr[i] = run;
        g_cursor[i] = run;
        run += g_cnt[i];
    }
    if (t == 1023) g_rowptr[NN] = ssum[1023];
}

__global__ void k_scatter(const int* __restrict__ ei,
                          const float* __restrict__ ew) {
    int e = blockIdx.x * blockDim.x + threadIdx.x;
    if (e < EE) {
        int is64 = g_is64;
        int s = edge_at(ei, is64, e);
        int d = edge_at(ei, is64, (long long)EE + e);
        if ((unsigned)s < (unsigned)NN && (unsigned)d < (unsigned)NN) {
            float nm = g_dinv[s] * ew[e] * g_dinv[d];
            int pos = atomicAdd(&g_cursor[d], 1);
            g_csr[pos] = make_int2(s, __float_as_int(nm));
        }
    }
}

// ------------------------- propagation (warp per node, fp16 gathers) --------
// F=64: lane owns one half2 (features 2*lane, 2*lane+1). 8-deep MLP chunks.
__global__ void k_prop64(int in_sel, int out_sel) {
    int gid = blockIdx.x * blockDim.x + threadIdx.x;
    int n = gid >> 5, lane = gid & 31;
    const __half2* h2 = (const __half2*)hbuf64(in_sel);
    __half2* o2 = (__half2*)g_hh[out_sel];
    int s0 = g_rowptr[n], s1 = g_rowptr[n + 1];
    float ax = 0.f, ay = 0.f;
    for (int base = s0; base < s1; base += 32) {
        int idx = base + lane;
        int2 ent = make_int2(0, 0);            // padding: ss=0, w=0
        if (idx < s1) ent = g_csr[idx];
        int rem = s1 - base;                   // > 0, warp-uniform
        #pragma unroll
        for (int jb = 0; jb < 32; jb += 8) {
            if (jb >= rem) break;
            #pragma unroll
            for (int u = 0; u < 8; u++) {
                int j = jb + u;
                int   ss = __shfl_sync(0xffffffffu, ent.x, j);
                float ww = __int_as_float(__shfl_sync(0xffffffffu, ent.y, j));
                float2 f = __half22float2(h2[ss * 32 + lane]);
                ax += ww * f.x;
                ay += ww * f.y;
            }
        }
    }
    o2[n * 32 + lane] = __floats2half2_rn(ax, ay);
}

// F=16: 8 lanes own half2 features (fp = lane&7), 4 edge slots (slot = lane>>3).
// in_sel < 0 -> external fp32 x; else fp16 g_x16h[in_sel].
__global__ void k_prop16(const float* __restrict__ xext, int in_sel, int out_sel) {
    int gid = blockIdx.x * blockDim.x + threadIdx.x;
    int n = gid >> 5, lane = gid & 31;
    int fp = lane & 7, slot = lane >> 3;
    const float2*  xin = (const float2*)xext;
    const __half2* hin = (const __half2*)g_x16h[(in_sel < 0) ? 0 : in_sel];
    bool use_x = (in_sel < 0);
    __half2* hout = (__half2*)g_x16h[out_sel];
    int s0 = g_rowptr[n], s1 = g_rowptr[n + 1];
    float ax = 0.f, ay = 0.f;
    for (int base = s0; base < s1; base += 32) {
        int idx = base + lane;
        int2 ent = make_int2(0, 0);
        if (idx < s1) ent = g_csr[idx];
        int rem = s1 - base;
        #pragma unroll
        for (int jb = 0; jb < 32; jb += 16) {
            if (jb >= rem) break;
            #pragma unroll
            for (int u = 0; u < 4; u++) {
                int j = jb + u * 4 + slot;
                int   ss = __shfl_sync(0xffffffffu, ent.x, j);
                float ww = __int_as_float(__shfl_sync(0xffffffffu, ent.y, j));
                float2 f;
                if (use_x) f = xin[ss * 8 + fp];
                else       f = __half22float2(hin[ss * 8 + fp]);
                ax += ww * f.x;
                ay += ww * f.y;
            }
        }
    }
    // reduce across the 4 slots (xor 8, xor 16)
    ax += __shfl_xor_sync(0xffffffffu, ax, 8);
    ay += __shfl_xor_sync(0xffffffffu, ay, 8);
    ax += __shfl_xor_sync(0xffffffffu, ax, 16);
    ay += __shfl_xor_sync(0xffffffffu, ay, 16);
    if (lane < 8) hout[n * 8 + fp] = __floats2half2_rn(ax, ay);
}

// ------------------------- fused hop-GEMM + bias + LeakyReLU ----------------
// out[n][j] = leaky( b[j] + sum_{k=0..4} sum_i h_k[n][i] * W[k][i][j] )
// hop0 fp32, hops 1..4 fp16. tile 128 nodes x 64 j; thread 8 nodes x 4 j.

__device__ __forceinline__ float4 load4f(const float* p) {
    return *(const float4*)p;
}
__device__ __forceinline__ float4 load4h(const __half* p) {
    __half2 a = *(const __half2*)p;
    __half2 c = *(const __half2*)(p + 2);
    float2 fa = __half22float2(a), fc = __half22float2(c);
    return make_float4(fa.x, fa.y, fc.x, fc.y);
}

template <int F>
__device__ __forceinline__ void mm_body(const float* __restrict__ h0,
                                        const __half* __restrict__ hh0,
                                        const __half* __restrict__ hh1,
                                        const __half* __restrict__ hh2,
                                        const __half* __restrict__ hh3,
                                        const float* __restrict__ W,
                                        const float* __restrict__ b,
                                        float* __restrict__ out,
                                        __half* __restrict__ outh,
                                        float* shW) {
    const __half* hhs[4] = {hh0, hh1, hh2, hh3};
    int t  = threadIdx.x;
    int n0 = blockIdx.x * 128;
    int tn = (t & 15) * 8;
    int tj = (t >> 4) * 4;

    float acc[8][4];
    #pragma unroll
    for (int p = 0; p < 8; p++)
        #pragma unroll
        for (int jj = 0; jj < 4; jj++) acc[p][jj] = 0.f;

    for (int k = 0; k < 5; k++) {
        __syncthreads();
        {
            const float4* Wk  = (const float4*)(W + k * F * 64);
            float4*       sh4 = (float4*)shW;
            for (int idx = t; idx < F * 16; idx += 256) sh4[idx] = Wk[idx];
        }
        __syncthreads();
        for (int ic = 0; ic < F / 4; ic++) {
            float4 a[8];
            #pragma unroll
            for (int p = 0; p < 8; p++) {
                int n = n0 + tn + p;
                if (n < NN) {
                    a[p] = (k == 0) ? load4f(h0 + (size_t)n * F + ic * 4)
                                    : load4h(hhs[k - 1] + (size_t)n * F + ic * 4);
                } else {
                    a[p] = make_float4(0.f, 0.f, 0.f, 0.f);
                }
            }
            #pragma unroll
            for (int q = 0; q < 4; q++) {
                int i = ic * 4 + q;
                float4 bv = *(const float4*)(shW + i * 64 + tj);
                #pragma unroll
                for (int p = 0; p < 8; p++) {
                    float av = (q == 0) ? a[p].x : (q == 1) ? a[p].y
                             : (q == 2) ? a[p].z : a[p].w;
                    acc[p][0] += av * bv.x;
                    acc[p][1] += av * bv.y;
                    acc[p][2] += av * bv.z;
                    acc[p][3] += av * bv.w;
                }
            }
        }
    }
    float4 bb = *(const float4*)(b + tj);
    #pragma unroll
    for (int p = 0; p < 8; p++) {
        int n = n0 + tn + p;
        if (n < NN) {
            float4 y;
            y.x = acc[p][0] + bb.x;  y.x = (y.x >= 0.f) ? y.x : 0.01f * y.x;
            y.y = acc[p][1] + bb.y;  y.y = (y.y >= 0.f) ? y.y : 0.01f * y.y;
            y.z = acc[p][2] + bb.z;  y.z = (y.z >= 0.f) ? y.z : 0.01f * y.z;
            y.w = acc[p][3] + bb.w;  y.w = (y.w >= 0.f) ? y.w : 0.01f * y.w;
            *(float4*)(out + (size_t)n * 64 + tj) = y;
            __half2* oh = (__half2*)(outh + (size_t)n * 64 + tj);
            oh[0] = __floats2half2_rn(y.x, y.y);
            oh[1] = __floats2half2_rn(y.z, y.w);
        }
    }
}

// layer 1: hop0 = x (fp32), hops = g_x16h[0..3]; writes outA + shadow
__global__ void k_mm16(const float* __restrict__ x,
                       const float* __restrict__ W,
                       const float* __restrict__ b) {
    __shared__ float shW[16 * 64];
    mm_body<16>(x, g_x16h[0], g_x16h[1], g_x16h[2], g_x16h[3],
                W, b, g_outA, g_outAh, shW);
}

// layers 2/3: hop0 = outA/outB (fp32), hops = g_hh[0..3]; writes out + shadow
__global__ void k_mm64(int in_sel, const float* __restrict__ W,
                       const float* __restrict__ b, int out_sel) {
    __shared__ float shW[64 * 64];
    const float* h0   = (in_sel == 4) ? g_outA : g_outB;
    float*       out  = (out_sel == 4) ? g_outA : g_outB;
    __half*      outh = (out_sel == 4) ? g_outAh : g_outBh;
    mm_body<64>(h0, g_hh[0], g_hh[1], g_hh[2], g_hh[3], W, b, out, outh, shW);
}

// ------------------------- final linear head (reads g_outA fp32) ------------
__global__ void k_final(const float* __restrict__ Wout,
                        const float* __restrict__ bout,
                        float* __restrict__ out) {
    int gid = blockIdx.x * blockDim.x + threadIdx.x;
    int n = gid >> 5, lane = gid & 31;
    float2 v = ((const float2*)g_outA)[n * 32 + lane];
    float2 w = ((const float2*)Wout)[lane];
    float a = v.x * w.x + v.y * w.y;
    #pragma unroll
    for (int off = 16; off > 0; off >>= 1)
        a += __shfl_xor_sync(0xffffffffu, a, off);
    if (lane == 0) out[n] = a + bout[0];
}

// ------------------------- launch -------------------------------------------
extern "C" void kernel_launch(void* const* d_in, const int* in_sizes, int n_in,
                              void* d_out, int out_size) {
    const float* x    = (const float*)d_in[0];
    const int*   ei   = (const int*)d_in[1];     // dtype auto-detected
    const float* ew   = (const float*)d_in[2];
    const float* W1   = (const float*)d_in[4];
    const float* b1   = (const float*)d_in[5];
    const float* W2   = (const float*)d_in[6];
    const float* b2   = (const float*)d_in[7];
    const float* Wout = (const float*)d_in[8];
    const float* bout = (const float*)d_in[9];
    float*       out  = (float*)d_out;

    const int NB_N = (NN + 255) / 256;
    const int NB_E = (EE + 255) / 256;
    const int NB_W = (NN * 32) / 256;       // warp-per-node: 12500 blocks
    const int NB_M = (NN + 127) / 128;      // mm kernels: 782 blocks

    // dtype detect + CSR + norm build
    k_detect <<<1, 1>>>(ei);
    k_init   <<<NB_N, 256>>>();
    k_degcnt <<<NB_E, 256>>>(ei, ew);
    k_dinv   <<<NB_N, 256>>>();
    k_scan   <<<1, 1024>>>();
    k_scatter<<<NB_E, 256>>>(ei, ew);

    // Layer 1 (F_IN=16 -> 64): hops in g_x16h, out -> outA(+shadow)
    k_prop16<<<NB_W, 256>>>(x, -1, 0);
    k_prop16<<<NB_W, 256>>>(x,  0, 1);
    k_prop16<<<NB_W, 256>>>(x,  1, 2);
    k_prop16<<<NB_W, 256>>>(x,  2, 3);
    k_mm16  <<<NB_M, 256>>>(x, W1, b1);

    // Layer 2 (64 -> 64): in A(4) -> out B(5)
    k_prop64<<<NB_W, 256>>>(4, 0);
    k_prop64<<<NB_W, 256>>>(0, 1);
    k_prop64<<<NB_W, 256>>>(1, 2);
    k_prop64<<<NB_W, 256>>>(2, 3);
    k_mm64  <<<NB_M, 256>>>(4, W2, b2, 5);

    // Layer 3 (64 -> 64): in B(5) -> out A(4)
    k_prop64<<<NB_W, 256>>>(5, 0);
    k_prop64<<<NB_W, 256>>>(0, 1);
    k_prop64<<<NB_W, 256>>>(1, 2);
    k_prop64<<<NB_W, 256>>>(2, 3);
    k_mm64  <<<NB_M, 256>>>(5, W2 + 5 * 64 * 64, b2 + 64, 4);

    // Regression head (reads g_outA fp32)
    k_final<<<NB_W, 256>>>(Wout, bout, out);
}

// round 8
// speedup vs baseline: 1.1256x; 1.1002x over previous
#include <cuda_runtime.h>
#include <cuda_fp16.h>

#define NN 100000
#define EE 3200000
#define SCAN_B 391           // ceil(NN/256)

// ------------------------- scratch (static device memory) -------------------
__device__ float  g_deg[NN];
__device__ float  g_dinv[NN];
__device__ int    g_cnt[NN];
__device__ int    g_rowptr[NN + 1];
__device__ int    g_cursor[NN];
__device__ int    g_bsum[SCAN_B];
__device__ int    g_boff[SCAN_B];
__device__ int2   g_csr[EE];             // (src, norm bits), grouped by dst
__device__ __half g_x16h[4][NN * 16];    // layer-1 hops h1..h4 (F=16, fp16)
__device__ __half g_hh[4][NN * 64];      // hidden hops h1..h4 (F=64, fp16)
__device__ float  g_outA[NN * 64];       // layer outputs ping (fp32)
__device__ float  g_outB[NN * 64];       // layer outputs pong (fp32)
__device__ __half g_outAh[NN * 64];      // fp16 shadow of outA
__device__ __half g_outBh[NN * 64];      // fp16 shadow of outB
__device__ int    g_is64;                // edge_index dtype flag (1 = int64)

// fp16 buffer selector: 0..3 -> g_hh[k], 4 -> g_outAh, 5 -> g_outBh
__device__ __forceinline__ const __half* hbuf64(int s) {
    switch (s) {
        case 0: return g_hh[0];
        case 1: return g_hh[1];
        case 2: return g_hh[2];
        case 3: return g_hh[3];
        case 4: return g_outAh;
        default: return g_outBh;
    }
}

__device__ __forceinline__ int edge_at(const int* ei, int is64, long long pos) {
    if (is64) return (int)((const long long*)ei)[pos];
    return ei[pos];
}

// packed fp32x2 helpers (sm_103a dual-FMA pipe, full fp32 precision)
__device__ __forceinline__ void fma2(unsigned long long& d,
                                     unsigned long long a,
                                     unsigned long long b) {
    asm("fma.rn.f32x2 %0, %1, %2, %0;" : "+l"(d) : "l"(a), "l"(b));
}
__device__ __forceinline__ unsigned long long pack2(float x, float y) {
    unsigned long long r;
    asm("mov.b64 %0, {%1, %2};" : "=l"(r) : "f"(x), "f"(y));
    return r;
}
__device__ __forceinline__ float2 unpack2(unsigned long long v) {
    float lo, hi;
    asm("mov.b64 {%0, %1}, %2;" : "=f"(lo), "=f"(hi) : "l"(v));
    return make_float2(lo, hi);
}

// ------------------------- init + dtype detect -------------------------------
__global__ void k_pre(const int* __restrict__ ei) {
    int i = blockIdx.x * blockDim.x + threadIdx.x;
    if (i < NN) { g_deg[i] = 0.f; g_cnt[i] = 0; }
    if (i == 0) {
        int odd_nonzero = 0;
        #pragma unroll
        for (int j = 0; j < 16; j++)
            if (ei[2 * j + 1] != 0) odd_nonzero = 1;
        g_is64 = odd_nonzero ? 0 : 1;
    }
}

// ------------------------- CSR build ----------------------------------------
__global__ void k_degcnt(const int* __restrict__ ei,
                         const float* __restrict__ ew) {
    int e = blockIdx.x * blockDim.x + threadIdx.x;
    if (e < EE) {
        int is64 = g_is64;
        int d = edge_at(ei, is64, (long long)EE + e);
        if ((unsigned)d < (unsigned)NN) {
            atomicAdd(&g_deg[d], ew[e]);
            atomicAdd(&g_cnt[d], 1);
        }
    }
}

// phase A: dinv elementwise + per-block(256) count sums (coalesced)
__global__ void k_scanA() {
    int i = blockIdx.x * 256 + threadIdx.x;
    int c = 0;
    if (i < NN) {
        float d = g_deg[i];
        g_dinv[i] = (d > 0.f) ? rsqrtf(d) : 0.f;
        c = g_cnt[i];
    }
    #pragma unroll
    for (int off = 16; off > 0; off >>= 1)
        c += __shfl_down_sync(0xffffffffu, c, off);
    __shared__ int ws[8];
    int lane = threadIdx.x & 31, wid = threadIdx.x >> 5;
    if (lane == 0) ws[wid] = c;
    __syncthreads();
    if (threadIdx.x < 8) {
        int v = ws[threadIdx.x];
        #pragma unroll
        for (int off = 4; off > 0; off >>= 1)
            v += __shfl_down_sync(0xffu, v, off);
        if (threadIdx.x == 0) g_bsum[blockIdx.x] = v;
    }
}

// phase B: single block scans the 391 block sums (exclusive offsets)
__global__ void k_scanB() {
    __shared__ int s[512];
    int t = threadIdx.x;
    int v = (t < SCAN_B) ? g_bsum[t] : 0;
    s[t] = v;
    __syncthreads();
    for (int off = 1; off < 512; off <<= 1) {
        int a = (t >= off) ? s[t - off] : 0;
        __syncthreads();
        s[t] += a;
        __syncthreads();
    }
    if (t < SCAN_B) g_boff[t] = s[t] - v;     // exclusive
    if (t == SCAN_B - 1) g_rowptr[NN] = s[t]; // total
}

// phase C: block-local scan + global offset -> rowptr/cursor (coalesced)
__global__ void k_scanC() {
    __shared__ int s[256];
    int t = threadIdx.x;
    int i = blockIdx.x * 256 + t;
    int v = (i < NN) ? g_cnt[i] : 0;
    s[t] = v;
    __syncthreads();
    for (int off = 1; off < 256; off <<= 1) {
        int a = (t >= off) ? s[t - off] : 0;
        __syncthreads();
        s[t] += a;
        __syncthreads();
    }
    int excl = s[t] - v + g_boff[blockIdx.x];
    if (i < NN) { g_rowptr[i] = excl; g_cursor[i] = excl; }
}

__global__ void k_scatter(const int* __restrict__ ei,
                          const float* __restrict__ ew) {
    int e = blockIdx.x * blockDim.x + threadIdx.x;
    if (e < EE) {
        int is64 = g_is64;
        int s = edge_at(ei, is64, e);
        int d = edge_at(ei, is64, (long long)EE + e);
        if ((unsigned)s < (unsigned)NN && (unsigned)d < (unsigned)NN) {
            float nm = g_dinv[s] * ew[e] * g_dinv[d];
            int pos = atomicAdd(&g_cursor[d], 1);
            g_csr[pos] = make_int2(s, __float_as_int(nm));
        }
    }
}

// ------------------------- propagation (warp per node, fp16 gathers) --------
__global__ void k_prop64(int in_sel, int out_sel) {
    int gid = blockIdx.x * blockDim.x + threadIdx.x;
    int n = gid >> 5, lane = gid & 31;
    const __half2* h2 = (const __half2*)hbuf64(in_sel);
    __half2* o2 = (__half2*)g_hh[out_sel];
    int s0 = g_rowptr[n], s1 = g_rowptr[n + 1];
    float ax = 0.f, ay = 0.f;
    for (int base = s0; base < s1; base += 32) {
        int idx = base + lane;
        int2 ent = make_int2(0, 0);
        if (idx < s1) ent = g_csr[idx];
        int rem = s1 - base;
        #pragma unroll
        for (int jb = 0; jb < 32; jb += 8) {
            if (jb >= rem) break;
            #pragma unroll
            for (int u = 0; u < 8; u++) {
                int j = jb + u;
                int   ss = __shfl_sync(0xffffffffu, ent.x, j);
                float ww = __int_as_float(__shfl_sync(0xffffffffu, ent.y, j));
                float2 f = __half22float2(h2[ss * 32 + lane]);
                ax += ww * f.x;
                ay += ww * f.y;
            }
        }
    }
    o2[n * 32 + lane] = __floats2half2_rn(ax, ay);
}

__global__ void k_prop16(const float* __restrict__ xext, int in_sel, int out_sel) {
    int gid = blockIdx.x * blockDim.x + threadIdx.x;
    int n = gid >> 5, lane = gid & 31;
    int fp = lane & 7, slot = lane >> 3;
    const float2*  xin = (const float2*)xext;
    const __half2* hin = (const __half2*)g_x16h[(in_sel < 0) ? 0 : in_sel];
    bool use_x = (in_sel < 0);
    __half2* hout = (__half2*)g_x16h[out_sel];
    int s0 = g_rowptr[n], s1 = g_rowptr[n + 1];
    float ax = 0.f, ay = 0.f;
    for (int base = s0; base < s1; base += 32) {
        int idx = base + lane;
        int2 ent = make_int2(0, 0);
        if (idx < s1) ent = g_csr[idx];
        int rem = s1 - base;
        #pragma unroll
        for (int jb = 0; jb < 32; jb += 16) {
            if (jb >= rem) break;
            #pragma unroll
            for (int u = 0; u < 4; u++) {
                int j = jb + u * 4 + slot;
                int   ss = __shfl_sync(0xffffffffu, ent.x, j);
                float ww = __int_as_float(__shfl_sync(0xffffffffu, ent.y, j));
                float2 f;
                if (use_x) f = xin[ss * 8 + fp];
                else       f = __half22float2(hin[ss * 8 + fp]);
                ax += ww * f.x;
                ay += ww * f.y;
            }
        }
    }
    ax += __shfl_xor_sync(0xffffffffu, ax, 8);
    ay += __shfl_xor_sync(0xffffffffu, ay, 8);
    ax += __shfl_xor_sync(0xffffffffu, ax, 16);
    ay += __shfl_xor_sync(0xffffffffu, ay, 16);
    if (lane < 8) hout[n * 8 + fp] = __floats2half2_rn(ax, ay);
}

// ------------------------- fused hop-GEMM (f32x2 pipe) ----------------------
// out[n][j] = leaky( b[j] + sum_k sum_i h_k[n][i] * W[k][i][j] )
// block: 256 threads = 256 nodes x 64 j; thread: 8 nodes x 8 j (4 j-pairs).
__device__ __forceinline__ float4 load4f(const float* p) {
    return *(const float4*)p;
}
__device__ __forceinline__ float4 load4h(const __half* p) {
    __half2 a = *(const __half2*)p;
    __half2 c = *(const __half2*)(p + 2);
    float2 fa = __half22float2(a), fc = __half22float2(c);
    return make_float4(fa.x, fa.y, fc.x, fc.y);
}

template <int F>
__device__ __forceinline__ void mm_body(const float* __restrict__ h0,
                                        const __half* __restrict__ hh0,
                                        const __half* __restrict__ hh1,
                                        const __half* __restrict__ hh2,
                                        const __half* __restrict__ hh3,
                                        const float* __restrict__ W,
                                        const float* __restrict__ b,
                                        float* __restrict__ out,
                                        __half* __restrict__ outh,
                                        float* shW) {
    const __half* hhs[4] = {hh0, hh1, hh2, hh3};
    int t  = threadIdx.x;
    int n0 = blockIdx.x * 256;
    int tn = (t & 31) * 8;          // 32 node-groups
    int tj = (t >> 5) * 8;          // 8 j-groups

    unsigned long long acc2[8][4];
    #pragma unroll
    for (int p = 0; p < 8; p++)
        #pragma unroll
        for (int jp = 0; jp < 4; jp++) acc2[p][jp] = 0ULL;

    for (int k = 0; k < 5; k++) {
        __syncthreads();
        {
            const float4* Wk  = (const float4*)(W + k * F * 64);
            float4*       sh4 = (float4*)shW;
            for (int idx = t; idx < F * 16; idx += 256) sh4[idx] = Wk[idx];
        }
        __syncthreads();
        const unsigned long long* shW2 = (const unsigned long long*)shW;
        for (int ic = 0; ic < F / 4; ic++) {
            float4 a[8];
            #pragma unroll
            for (int p = 0; p < 8; p++) {
                int n = n0 + tn + p;
                if (n < NN) {
                    a[p] = (k == 0) ? load4f(h0 + (size_t)n * F + ic * 4)
                                    : load4h(hhs[k - 1] + (size_t)n * F + ic * 4);
                } else {
                    a[p] = make_float4(0.f, 0.f, 0.f, 0.f);
                }
            }
            #pragma unroll
            for (int q = 0; q < 4; q++) {
                int i = ic * 4 + q;
                unsigned long long w2[4];
                #pragma unroll
                for (int jp = 0; jp < 4; jp++)
                    w2[jp] = shW2[(i * 64 + tj) / 2 + jp];
                #pragma unroll
                for (int p = 0; p < 8; p++) {
                    float av = (q == 0) ? a[p].x : (q == 1) ? a[p].y
                             : (q == 2) ? a[p].z : a[p].w;
                    unsigned long long av2 = pack2(av, av);
                    #pragma unroll
                    for (int jp = 0; jp < 4; jp++)
                        fma2(acc2[p][jp], av2, w2[jp]);
                }
            }
        }
    }
    float bb[8];
    #pragma unroll
    for (int jj = 0; jj < 8; jj++) bb[jj] = b[tj + jj];
    #pragma unroll
    for (int p = 0; p < 8; p++) {
        int n = n0 + tn + p;
        if (n < NN) {
            float y[8];
            #pragma unroll
            for (int jp = 0; jp < 4; jp++) {
                float2 v = unpack2(acc2[p][jp]);
                y[jp * 2]     = v.x + bb[jp * 2];
                y[jp * 2 + 1] = v.y + bb[jp * 2 + 1];
            }
            #pragma unroll
            for (int jj = 0; jj < 8; jj++)
                y[jj] = (y[jj] >= 0.f) ? y[jj] : 0.01f * y[jj];
            float4* o4 = (float4*)(out + (size_t)n * 64 + tj);
            o4[0] = make_float4(y[0], y[1], y[2], y[3]);
            o4[1] = make_float4(y[4], y[5], y[6], y[7]);
            __half2* oh = (__half2*)(outh + (size_t)n * 64 + tj);
            #pragma unroll
            for (int jp = 0; jp < 4; jp++)
                oh[jp] = __floats2half2_rn(y[jp * 2], y[jp * 2 + 1]);
        }
    }
}

__global__ void k_mm16(const float* __restrict__ x,
                       const float* __restrict__ W,
                       const float* __restrict__ b) {
    __shared__ __align__(16) float shW[16 * 64];
    mm_body<16>(x, g_x16h[0], g_x16h[1], g_x16h[2], g_x16h[3],
                W, b, g_outA, g_outAh, shW);
}

__global__ void k_mm64(int in_sel, const float* __restrict__ W,
                       const float* __restrict__ b, int out_sel) {
    __shared__ __align__(16) float shW[64 * 64];
    const float* h0   = (in_sel == 4) ? g_outA : g_outB;
    float*       out  = (out_sel == 4) ? g_outA : g_outB;
    __half*      outh = (out_sel == 4) ? g_outAh : g_outBh;
    mm_body<64>(h0, g_hh[0], g_hh[1], g_hh[2], g_hh[3], W, b, out, outh, shW);
}

// ------------------------- final linear head (reads g_outA fp32) ------------
__global__ void k_final(const float* __restrict__ Wout,
                        const float* __restrict__ bout,
                        float* __restrict__ out) {
    int gid = blockIdx.x * blockDim.x + threadIdx.x;
    int n = gid >> 5, lane = gid & 31;
    float2 v = ((const float2*)g_outA)[n * 32 + lane];
    float2 w = ((const float2*)Wout)[lane];
    float a = v.x * w.x + v.y * w.y;
    #pragma unroll
    for (int off = 16; off > 0; off >>= 1)
        a += __shfl_xor_sync(0xffffffffu, a, off);
    if (lane == 0) out[n] = a + bout[0];
}

// ------------------------- launch -------------------------------------------
extern "C" void kernel_launch(void* const* d_in, const int* in_sizes, int n_in,
                              void* d_out, int out_size) {
    const float* x    = (const float*)d_in[0];
    const int*   ei   = (const int*)d_in[1];     // dtype auto-detected
    const float* ew   = (const float*)d_in[2];
    const float* W1   = (const float*)d_in[4];
    const float* b1   = (const float*)d_in[5];
    const float* W2   = (const float*)d_in[6];
    const float* b2   = (const float*)d_in[7];
    const float* Wout = (const float*)d_in[8];
    const float* bout = (const float*)d_in[9];
    float*       out  = (float*)d_out;

    const int NB_E = (EE + 255) / 256;
    const int NB_W = (NN * 32) / 256;       // warp-per-node: 12500 blocks
    const int NB_M = (NN + 255) / 256;      // mm kernels: 391 blocks

    // init + CSR build (coalesced 3-phase scan)
    k_pre    <<<SCAN_B, 256>>>(ei);
    k_degcnt <<<NB_E, 256>>>(ei, ew);
    k_scanA  <<<SCAN_B, 256>>>();
    k_scanB  <<<1, 512>>>();
    k_scanC  <<<SCAN_B, 256>>>();
    k_scatter<<<NB_E, 256>>>(ei, ew);

    // Layer 1 (F_IN=16 -> 64): hops in g_x16h, out -> outA(+shadow)
    k_prop16<<<NB_W, 256>>>(x, -1, 0);
    k_prop16<<<NB_W, 256>>>(x,  0, 1);
    k_prop16<<<NB_W, 256>>>(x,  1, 2);
    k_prop16<<<NB_W, 256>>>(x,  2, 3);
    k_mm16  <<<NB_M, 256>>>(x, W1, b1);

    // Layer 2 (64 -> 64): in A(4) -> out B(5)
    k_prop64<<<NB_W, 256>>>(4, 0);
    k_prop64<<<NB_W, 256>>>(0, 1);
    k_prop64<<<NB_W, 256>>>(1, 2);
    k_prop64<<<NB_W, 256>>>(2, 3);
    k_mm64  <<<NB_M, 256>>>(4, W2, b2, 5);

    // Layer 3 (64 -> 64): in B(5) -> out A(4)
    k_prop64<<<NB_W, 256>>>(5, 0);
    k_prop64<<<NB_W, 256>>>(0, 1);
    k_prop64<<<NB_W, 256>>>(1, 2);
    k_prop64<<<NB_W, 256>>>(2, 3);
    k_mm64  <<<NB_M, 256>>>(5, W2 + 5 * 64 * 64, b2 + 64, 4);

    // Regression head (reads g_outA fp32)
    k_final<<<NB_W, 256>>>(Wout, bout, out);
}